// round 4
// baseline (speedup 1.0000x reference)
#include <cuda_runtime.h>
#include <cuda_bf16.h>
#include <math.h>

// Problem constants
#define S_  32
#define D_  600
#define H_  600
#define A_  6
#define E_  1024
#define T_  50
#define B_  1024

// Scratch (device globals; allocation is forbidden)
__device__ float g_enc[T_ * B_ * H_];    // precomputed enc_t @ Wq1[:,D:]^T
__device__ float g_rnn[B_ * H_];
__device__ float g_gi[B_ * 3 * D_];
__device__ float g_gh[B_ * 3 * D_];
__device__ float g_hp[B_ * H_];
__device__ float g_hq[B_ * H_];

__device__ __forceinline__ float eluf(float x) { return x > 0.f ? x : expm1f(x); }
__device__ __forceinline__ float sigmoidf_(float x) { return 1.f / (1.f + expf(-x)); }
__device__ __forceinline__ float softplusf_(float x) {
    return fmaxf(x, 0.f) + log1pf(expf(-fabsf(x)));
}

// ---------------------------------------------------------------------------
// K1: rnn_in = elu([act | stoch] @ W_in^T + b_in)   M=B, N=H, K=38
// ---------------------------------------------------------------------------
__global__ void rnn_in_kernel(const float* __restrict__ act,
                              const float* __restrict__ stoch,
                              const float* __restrict__ W_in,
                              const float* __restrict__ b_in,
                              float* __restrict__ out) {
    int b = blockIdx.y;
    int h = blockIdx.x * 128 + threadIdx.x;
    __shared__ float x[A_ + S_];
    if (threadIdx.x < A_) x[threadIdx.x] = act[b * A_ + threadIdx.x];
    else if (threadIdx.x < A_ + S_) x[threadIdx.x] = stoch[b * S_ + threadIdx.x - A_];
    __syncthreads();
    if (h < H_) {
        float acc = b_in[h];
        const float* w = W_in + h * (A_ + S_);
#pragma unroll
        for (int k = 0; k < A_ + S_; k++) acc = fmaf(x[k], w[k], acc);
        out[b * H_ + h] = eluf(acc);
    }
}

// ---------------------------------------------------------------------------
// Generic batched GEMM: C[M,N] = A[M,K] @ W[N,K]^T (+bias) (+add) (EPI: elu)
// Two param sets selected by blockIdx.z. Tile 128x64, BK=8, 256 threads, 8x4.
// Double-buffered smem pipeline; vectorized float4 epilogue.
// Requires: M % 128 == 0, N % 4 == 0, K % 8 == 0, lda % 4 == 0, ldw % 2 == 0.
// ---------------------------------------------------------------------------
struct GP {
    const float* A;
    const float* W;
    const float* bias;   // may be null
    const float* add;    // may be null, layout [M, N]
    float* C;
    int N;
    int ldw;
};

template <int EPI>
__global__ __launch_bounds__(256) void gemm_tn(GP p0, GP p1, int K, int lda) {
    GP p = (blockIdx.z == 0) ? p0 : p1;
    const int bm = blockIdx.y * 128;
    const int bn = blockIdx.x * 64;

    __shared__ float As[2][8][132];
    __shared__ float Ws[2][8][68];

    const int tid = threadIdx.x;
    const int tx = tid % 16;        // n micro
    const int ty = tid / 16;        // m micro
    const int alr = tid / 2;        // A tile row 0..127
    const int alk = (tid % 2) * 4;  // A tile k 0 or 4
    const int wlr = tid / 4;        // W tile row 0..63
    const int wlk = (tid % 4) * 2;  // W tile k 0,2,4,6

    float acc[8][4];
#pragma unroll
    for (int i = 0; i < 8; i++)
#pragma unroll
        for (int j = 0; j < 4; j++) acc[i][j] = 0.f;

    const float* __restrict__ Abase = p.A + (bm + alr) * lda + alk;
    const int wn = bn + wlr;
    const float* __restrict__ Wbase = p.W + wn * p.ldw + wlk;
    const bool wvalid = (wn < p.N);

    const int nslabs = K / 8;

    // Prologue: load slab 0 into buffer 0
    {
        float4 av = *(const float4*)(Abase);
        As[0][alk + 0][alr] = av.x;
        As[0][alk + 1][alr] = av.y;
        As[0][alk + 2][alr] = av.z;
        As[0][alk + 3][alr] = av.w;
        float2 wv = make_float2(0.f, 0.f);
        if (wvalid) wv = *(const float2*)(Wbase);
        Ws[0][wlk + 0][wlr] = wv.x;
        Ws[0][wlk + 1][wlr] = wv.y;
    }
    __syncthreads();

    for (int s = 0; s < nslabs; s++) {
        const int cur = s & 1;
        const int nxt = cur ^ 1;

        // Prefetch next slab to registers (overlaps with compute below)
        float4 av;
        float2 wv;
        const bool have_next = (s + 1 < nslabs);
        if (have_next) {
            const int k0 = (s + 1) * 8;
            av = *(const float4*)(Abase + k0);
            wv = make_float2(0.f, 0.f);
            if (wvalid) wv = *(const float2*)(Wbase + k0);
        }

        // Compute on current buffer
#pragma unroll
        for (int kk = 0; kk < 8; kk++) {
            float4 a0 = *(const float4*)&As[cur][kk][ty * 8];
            float4 a1 = *(const float4*)&As[cur][kk][ty * 8 + 4];
            float4 b = *(const float4*)&Ws[cur][kk][tx * 4];
            float am[8] = {a0.x, a0.y, a0.z, a0.w, a1.x, a1.y, a1.z, a1.w};
            float bn_[4] = {b.x, b.y, b.z, b.w};
#pragma unroll
            for (int i = 0; i < 8; i++)
#pragma unroll
                for (int j = 0; j < 4; j++) acc[i][j] = fmaf(am[i], bn_[j], acc[i][j]);
        }

        // Store prefetched slab to the alternate buffer
        if (have_next) {
            As[nxt][alk + 0][alr] = av.x;
            As[nxt][alk + 1][alr] = av.y;
            As[nxt][alk + 2][alr] = av.z;
            As[nxt][alk + 3][alr] = av.w;
            Ws[nxt][wlk + 0][wlr] = wv.x;
            Ws[nxt][wlk + 1][wlr] = wv.y;
        }
        __syncthreads();
    }

    // Vectorized epilogue: N % 4 == 0 and n0 % 4 == 0 always hold here.
    const int m0 = bm + ty * 8;
    const int n0 = bn + tx * 4;
    if (n0 >= p.N) return;

    float4 bias4 = make_float4(0.f, 0.f, 0.f, 0.f);
    if (p.bias) bias4 = *(const float4*)(p.bias + n0);

#pragma unroll
    for (int i = 0; i < 8; i++) {
        const int m = m0 + i;
        float4 v = make_float4(acc[i][0] + bias4.x, acc[i][1] + bias4.y,
                               acc[i][2] + bias4.z, acc[i][3] + bias4.w);
        if (p.add) {
            float4 a4 = *(const float4*)(p.add + (long)m * p.N + n0);
            v.x += a4.x; v.y += a4.y; v.z += a4.z; v.w += a4.w;
        }
        if (EPI == 1) {
            v.x = eluf(v.x); v.y = eluf(v.y); v.z = eluf(v.z); v.w = eluf(v.w);
        }
        *(float4*)(p.C + (long)m * p.N + n0) = v;
    }
}

// ---------------------------------------------------------------------------
// K3: GRU elementwise gate combine, float4-vectorized (D % 4 == 0)
// ---------------------------------------------------------------------------
__global__ void gru_elem(const float* __restrict__ gi, const float* __restrict__ gh,
                         const float* __restrict__ hprev,
                         float* __restrict__ det1, float* __restrict__ det2) {
    const int D4 = D_ / 4;
    int i = blockIdx.x * blockDim.x + threadIdx.x;   // float4 index
    if (i >= B_ * D4) return;
    int b = i / D4;
    int d4 = i - b * D4;
    const float4* gib = (const float4*)(gi + b * 3 * D_);
    const float4* ghb = (const float4*)(gh + b * 3 * D_);
    float4 ir = gib[d4],            hr = ghb[d4];
    float4 iz = gib[D4 + d4],       hz = ghb[D4 + d4];
    float4 in_ = gib[2 * D4 + d4],  hn = ghb[2 * D4 + d4];
    float4 h = ((const float4*)(hprev + b * D_))[d4];

    float4 o;
    {
        float r = sigmoidf_(ir.x + hr.x);
        float z = sigmoidf_(iz.x + hz.x);
        float n = tanhf(fmaf(r, hn.x, in_.x));
        o.x = fmaf(z, h.x - n, n);
    }
    {
        float r = sigmoidf_(ir.y + hr.y);
        float z = sigmoidf_(iz.y + hz.y);
        float n = tanhf(fmaf(r, hn.y, in_.y));
        o.y = fmaf(z, h.y - n, n);
    }
    {
        float r = sigmoidf_(ir.z + hr.z);
        float z = sigmoidf_(iz.z + hz.z);
        float n = tanhf(fmaf(r, hn.z, in_.z));
        o.z = fmaf(z, h.z - n, n);
    }
    {
        float r = sigmoidf_(ir.w + hr.w);
        float z = sigmoidf_(iz.w + hz.w);
        float n = tanhf(fmaf(r, hn.w, in_.w));
        o.w = fmaf(z, h.w - n, n);
    }
    ((float4*)(det1 + b * D_))[d4] = o;
    ((float4*)(det2 + b * D_))[d4] = o;
}

// ---------------------------------------------------------------------------
// K5: heads. C[1024,64] = A @ W2^T, split mean/std, softplus+MIN_STD, noise.
// Tile 64x64 (N=64 exactly), stage in smem for cross-column pairing.
// ---------------------------------------------------------------------------
struct HeadP {
    const float* A;     // [B, 600]
    const float* W;     // [64, 600]
    const float* bias;  // [64]
    const float* eps;   // [B, 32]
    float* om;          // mean      [B,32]
    float* os;          // std       [B,32]
    float* ost;         // sample    [B,32]
};

__global__ __launch_bounds__(256) void heads_kernel(HeadP h0, HeadP h1) {
    HeadP p = (blockIdx.z == 0) ? h0 : h1;
    const int bm = blockIdx.y * 64;
    __shared__ float As[8][68];
    __shared__ float Ws[8][68];
    __shared__ float Cs[64][65];

    const int tid = threadIdx.x;
    const int tx = tid % 16;
    const int ty = tid / 16;
    const int lr = tid / 4;
    const int lk = (tid % 4) * 2;

    float acc[4][4];
#pragma unroll
    for (int i = 0; i < 4; i++)
#pragma unroll
        for (int j = 0; j < 4; j++) acc[i][j] = 0.f;

    const float* __restrict__ Abase = p.A + (bm + lr) * H_ + lk;
    const float* __restrict__ Wbase = p.W + lr * H_ + lk;

    for (int k0 = 0; k0 < H_; k0 += 8) {
        float2 av = *(const float2*)(Abase + k0);
        As[lk][lr] = av.x;
        As[lk + 1][lr] = av.y;
        float2 wv = *(const float2*)(Wbase + k0);
        Ws[lk][lr] = wv.x;
        Ws[lk + 1][lr] = wv.y;
        __syncthreads();
#pragma unroll
        for (int kk = 0; kk < 8; kk++) {
            float4 a = *(const float4*)&As[kk][ty * 4];
            float4 b = *(const float4*)&Ws[kk][tx * 4];
            float am[4] = {a.x, a.y, a.z, a.w};
            float bn_[4] = {b.x, b.y, b.z, b.w};
#pragma unroll
            for (int i = 0; i < 4; i++)
#pragma unroll
                for (int j = 0; j < 4; j++) acc[i][j] = fmaf(am[i], bn_[j], acc[i][j]);
        }
        __syncthreads();
    }

#pragma unroll
    for (int i = 0; i < 4; i++)
#pragma unroll
        for (int j = 0; j < 4; j++) Cs[ty * 4 + i][tx * 4 + j] = acc[i][j];
    __syncthreads();

    for (int e = tid; e < 64 * S_; e += 256) {
        int m = e / S_;
        int c = e - m * S_;
        int b = bm + m;
        float mean = Cs[m][c] + p.bias[c];
        float psr = Cs[m][c + S_] + p.bias[c + S_];
        float std = softplusf_(psr) + 0.1f;
        float ep = p.eps[b * S_ + c];
        p.om[b * S_ + c] = mean;
        p.os[b * S_ + c] = std;
        p.ost[b * S_ + c] = fmaf(std, ep, mean);
    }
}

// ---------------------------------------------------------------------------
// Host side
// ---------------------------------------------------------------------------
extern "C" void kernel_launch(void* const* d_in, const int* in_sizes, int n_in,
                              void* d_out, int out_size) {
    const float* encoded   = (const float*)d_in[1];   // [T,B,E]
    const float* actions   = (const float*)d_in[2];   // [T,B,A]
    const float* init_stoch= (const float*)d_in[3];   // [B,S]
    const float* init_det  = (const float*)d_in[4];   // [B,D]
    const float* noise_p   = (const float*)d_in[5];   // [T,B,S]
    const float* noise_q   = (const float*)d_in[6];   // [T,B,S]
    const float* W_in      = (const float*)d_in[7];   // [H, A+S]
    const float* b_in      = (const float*)d_in[8];
    const float* W_ih      = (const float*)d_in[9];   // [3D, H]
    const float* W_hh      = (const float*)d_in[10];  // [3D, D]
    const float* b_ih      = (const float*)d_in[11];
    const float* b_hh      = (const float*)d_in[12];
    const float* Wp1       = (const float*)d_in[13];  // [H, D]
    const float* bp1       = (const float*)d_in[14];
    const float* Wp2       = (const float*)d_in[15];  // [2S, H]
    const float* bp2       = (const float*)d_in[16];
    const float* Wq1       = (const float*)d_in[17];  // [H, D+E]
    const float* bq1       = (const float*)d_in[18];
    const float* Wq2       = (const float*)d_in[19];  // [2S, H]
    const float* bq2       = (const float*)d_in[20];
    float* out = (float*)d_out;

    // Output layout: concat of flattened leaves
    const long TBS = (long)T_ * B_ * S_;
    const long TBD = (long)T_ * B_ * D_;
    float* o_pm    = out;
    float* o_ps    = out + TBS;
    float* o_prior = out + 2 * TBS;
    float* o_det1  = out + 3 * TBS;
    float* o_qm    = out + 3 * TBS + TBD;
    float* o_qs    = out + 4 * TBS + TBD;
    float* o_post  = out + 5 * TBS + TBD;
    float* o_det2  = out + 6 * TBS + TBD;

    float *p_enc, *p_rnn, *p_gi, *p_gh, *p_hp, *p_hq;
    cudaGetSymbolAddress((void**)&p_enc, g_enc);
    cudaGetSymbolAddress((void**)&p_rnn, g_rnn);
    cudaGetSymbolAddress((void**)&p_gi, g_gi);
    cudaGetSymbolAddress((void**)&p_gh, g_gh);
    cudaGetSymbolAddress((void**)&p_hp, g_hp);
    cudaGetSymbolAddress((void**)&p_hq, g_hq);

    // Precompute: g_enc[t*B + b, h] = encoded[t,b,:] @ Wq1[h, D:]^T
    {
        GP p;
        p.A = encoded; p.W = Wq1 + D_; p.bias = nullptr; p.add = nullptr;
        p.C = p_enc; p.N = H_; p.ldw = D_ + E_;
        dim3 grid((H_ + 63) / 64, (T_ * B_) / 128, 1);
        gemm_tn<0><<<grid, 256>>>(p, p, E_, E_);
    }

    for (int t = 0; t < T_; t++) {
        const float* stoch = (t == 0) ? init_stoch : (o_post + (long)(t - 1) * B_ * S_);
        const float* detp  = (t == 0) ? init_det   : (o_det1 + (long)(t - 1) * B_ * D_);
        float* det_t1 = o_det1 + (long)t * B_ * D_;
        float* det_t2 = o_det2 + (long)t * B_ * D_;

        // K1: rnn input
        rnn_in_kernel<<<dim3((H_ + 127) / 128, B_), 128>>>(
            actions + (long)t * B_ * A_, stoch, W_in, b_in, p_rnn);

        // K2: gi = rnn_in @ W_ih^T + b_ih ; gh = det @ W_hh^T + b_hh
        {
            GP p0, p1;
            p0.A = p_rnn; p0.W = W_ih; p0.bias = b_ih; p0.add = nullptr;
            p0.C = p_gi; p0.N = 3 * D_; p0.ldw = H_;
            p1.A = detp; p1.W = W_hh; p1.bias = b_hh; p1.add = nullptr;
            p1.C = p_gh; p1.N = 3 * D_; p1.ldw = D_;
            dim3 grid((3 * D_ + 63) / 64, B_ / 128, 2);
            gemm_tn<0><<<grid, 256>>>(p0, p1, H_, H_);
        }

        // K3: GRU combine -> det_new (written into both output slots)
        gru_elem<<<(B_ * (D_ / 4) + 255) / 256, 256>>>(p_gi, p_gh, detp, det_t1, det_t2);

        // K4: hp = elu(det @ Wp1^T + bp1); hq = elu(det @ Wq1[:, :D]^T + bq1 + enc_part)
        {
            GP p0, p1;
            p0.A = det_t1; p0.W = Wp1; p0.bias = bp1; p0.add = nullptr;
            p0.C = p_hp; p0.N = H_; p0.ldw = D_;
            p1.A = det_t1; p1.W = Wq1; p1.bias = bq1;
            p1.add = p_enc + (long)t * B_ * H_;
            p1.C = p_hq; p1.N = H_; p1.ldw = D_ + E_;
            dim3 grid((H_ + 63) / 64, B_ / 128, 2);
            gemm_tn<1><<<grid, 256>>>(p0, p1, D_, D_);
        }

        // K5: heads + noise
        {
            HeadP h0, h1;
            h0.A = p_hp; h0.W = Wp2; h0.bias = bp2;
            h0.eps = noise_p + (long)t * B_ * S_;
            h0.om = o_pm + (long)t * B_ * S_;
            h0.os = o_ps + (long)t * B_ * S_;
            h0.ost = o_prior + (long)t * B_ * S_;
            h1.A = p_hq; h1.W = Wq2; h1.bias = bq2;
            h1.eps = noise_q + (long)t * B_ * S_;
            h1.om = o_qm + (long)t * B_ * S_;
            h1.os = o_qs + (long)t * B_ * S_;
            h1.ost = o_post + (long)t * B_ * S_;
            dim3 grid(1, B_ / 64, 2);
            heads_kernel<<<grid, 256>>>(h0, h1);
        }
    }
}